// round 6
// baseline (speedup 1.0000x reference)
#include <cuda_runtime.h>

#define NN   20000
#define RR   32
#define EMB  16
#define HID  128
#define NE   600000
#define NRB  (NN*RR)          // 640000 (dst,rel) buckets

// ---- scratch (device globals; no allocation in kernel_launch) ----
__device__ float g_inv[NRB];                    // 1/count per (node, rel)
__device__ float g_m1 [NN*RR*EMB];              // layer-1 pre-aggregation  (41 MB)
__device__ float g_h1 [NN*HID];                 // layer-1 output           (10 MB)
__device__ float g_xr2[NN*RR*HID];              // layer-2 transformed feats (327 MB)
__device__ unsigned char g_used[NRB];           // (src, rel) pair appears on some edge

// ---------------------------------------------------------------- zero scratch
__global__ void k_zero() {
    int i  = blockIdx.x * blockDim.x + threadIdx.x;
    int st = gridDim.x * blockDim.x;
    for (int j = i; j < NN*RR*EMB; j += st) g_m1[j] = 0.f;
    for (int j = i; j < NRB;       j += st) { g_inv[j] = 0.f; g_used[j] = 0; }
}

// ---------------------------------------------------------------- edge counts + used mask
__global__ void k_count(const int* __restrict__ ei, const int* __restrict__ et) {
    int e = blockIdx.x * blockDim.x + threadIdx.x;
    if (e >= NE) return;
    int src = ei[e];
    int dst = ei[NE + e];
    int r   = et[e];
    atomicAdd(&g_inv[dst*RR + r], 1.f);
    g_used[src*RR + r] = 1;
}

__global__ void k_inv() {
    int i = blockIdx.x * blockDim.x + threadIdx.x;
    if (i >= NRB) return;
    float c = g_inv[i];
    g_inv[i] = (c > 0.f) ? 1.f / c : 0.f;
}

// ---------------------------------------------------------------- layer-1 edge scatter (4 thr/edge)
__global__ void k_scatter1(const int* __restrict__ ei, const int* __restrict__ et,
                           const float* __restrict__ x) {
    int idx = blockIdx.x * blockDim.x + threadIdx.x;
    if (idx >= NE * 4) return;
    int e = idx >> 2, q = idx & 3;
    int src = ei[e];
    int dst = ei[NE + e];
    int r   = et[e];
    float4 v = *(const float4*)&x[src*EMB + q*4];
    float* m = &g_m1[(dst*RR + r)*EMB + q*4];
    atomicAdd(m + 0, v.x); atomicAdd(m + 1, v.y);
    atomicAdd(m + 2, v.z); atomicAdd(m + 3, v.w);
}

// ---------------------------------------------------------------- layer-1 node GEMM
// h1 = relu( [inv-scaled m1 | x]  @  [W1 ; root1]  + b1 )
// M = 20000, K = 528 (33 steps of 16), N = 128.  Tile: 64 x 128, 256 threads.
__global__ void k_layer1(const float* __restrict__ x,  const float* __restrict__ W1,
                         const float* __restrict__ r1, const float* __restrict__ b1) {
    __shared__ float As[16][68];     // A^T tile (k, m), padded
    __shared__ float Bs[16][128];
    int m0  = blockIdx.x * 64;
    int tid = threadIdx.x;
    int tx  = tid & 31, ty = tid >> 5;
    int lm  = tid >> 2, cg = tid & 3;
    int ln  = m0 + lm;
    float acc[8][4];
    #pragma unroll
    for (int i = 0; i < 8; i++)
        #pragma unroll
        for (int j = 0; j < 4; j++) acc[i][j] = 0.f;

    for (int step = 0; step < 33; ++step) {
        float4 av = make_float4(0.f, 0.f, 0.f, 0.f);
        if (ln < NN) {
            if (step < 32) {
                float s = g_inv[ln*RR + step];
                if (s != 0.f) {
                    av = *(const float4*)&g_m1[ln*(RR*EMB) + step*EMB + cg*4];
                    av.x *= s; av.y *= s; av.z *= s; av.w *= s;
                }
            } else {
                av = *(const float4*)&x[ln*EMB + cg*4];
            }
        }
        const float* Bsrc = (step < 32) ? (W1 + step*(EMB*HID)) : r1;
        float4 bv0 = *(const float4*)&Bsrc[(tid*2 + 0)*4];
        float4 bv1 = *(const float4*)&Bsrc[(tid*2 + 1)*4];

        __syncthreads();
        As[cg*4 + 0][lm] = av.x; As[cg*4 + 1][lm] = av.y;
        As[cg*4 + 2][lm] = av.z; As[cg*4 + 3][lm] = av.w;
        {
            int q0 = tid*2, q1 = tid*2 + 1;
            *(float4*)&Bs[q0 >> 5][(q0 & 31)*4] = bv0;
            *(float4*)&Bs[q1 >> 5][(q1 & 31)*4] = bv1;
        }
        __syncthreads();

        #pragma unroll
        for (int k = 0; k < 16; k++) {
            float4 b  = *(const float4*)&Bs[k][tx*4];
            float4 a0 = *(const float4*)&As[k][ty*8];
            float4 a1 = *(const float4*)&As[k][ty*8 + 4];
            float a[8] = {a0.x, a0.y, a0.z, a0.w, a1.x, a1.y, a1.z, a1.w};
            float bb[4] = {b.x, b.y, b.z, b.w};
            #pragma unroll
            for (int i = 0; i < 8; i++)
                #pragma unroll
                for (int j = 0; j < 4; j++) acc[i][j] += a[i] * bb[j];
        }
    }
    #pragma unroll
    for (int i = 0; i < 8; i++) {
        int n = m0 + ty*8 + i;
        if (n < NN) {
            #pragma unroll
            for (int j = 0; j < 4; j++) {
                float v = acc[i][j] + b1[tx*4 + j];
                g_h1[n*HID + tx*4 + j] = fmaxf(v, 0.f);
            }
        }
    }
}

// ---------------------------------------------------------------- layer-2 transform GEMM
// blockIdx.y = r (< 32): xr2[:,r,:] = h1 @ W2[r]  (store only used (n,r) rows)
// blockIdx.y = 32      : out        = h1 @ root2 + b2   (base term; K6 atomics add on top)
__global__ void k_layer2(const float* __restrict__ W2, const float* __restrict__ r2,
                         const float* __restrict__ b2, float* __restrict__ out) {
    __shared__ float As[16][68];
    __shared__ float Bs[16][128];
    int m0  = blockIdx.x * 64;
    int r   = blockIdx.y;
    int tid = threadIdx.x;
    int tx  = tid & 31, ty = tid >> 5;
    int lm  = tid >> 2, cg = tid & 3;
    int ln  = m0 + lm;
    const float* Bbase = (r < 32) ? (W2 + r*(HID*HID)) : r2;
    float acc[8][4];
    #pragma unroll
    for (int i = 0; i < 8; i++)
        #pragma unroll
        for (int j = 0; j < 4; j++) acc[i][j] = 0.f;

    for (int step = 0; step < 8; ++step) {
        float4 av = make_float4(0.f, 0.f, 0.f, 0.f);
        if (ln < NN) av = *(const float4*)&g_h1[ln*HID + step*16 + cg*4];
        const float* Bsrc = Bbase + step*16*HID;
        float4 bv0 = *(const float4*)&Bsrc[(tid*2 + 0)*4];
        float4 bv1 = *(const float4*)&Bsrc[(tid*2 + 1)*4];

        __syncthreads();
        As[cg*4 + 0][lm] = av.x; As[cg*4 + 1][lm] = av.y;
        As[cg*4 + 2][lm] = av.z; As[cg*4 + 3][lm] = av.w;
        {
            int q0 = tid*2, q1 = tid*2 + 1;
            *(float4*)&Bs[q0 >> 5][(q0 & 31)*4] = bv0;
            *(float4*)&Bs[q1 >> 5][(q1 & 31)*4] = bv1;
        }
        __syncthreads();

        #pragma unroll
        for (int k = 0; k < 16; k++) {
            float4 b  = *(const float4*)&Bs[k][tx*4];
            float4 a0 = *(const float4*)&As[k][ty*8];
            float4 a1 = *(const float4*)&As[k][ty*8 + 4];
            float a[8] = {a0.x, a0.y, a0.z, a0.w, a1.x, a1.y, a1.z, a1.w};
            float bb[4] = {b.x, b.y, b.z, b.w};
            #pragma unroll
            for (int i = 0; i < 8; i++)
                #pragma unroll
                for (int j = 0; j < 4; j++) acc[i][j] += a[i] * bb[j];
        }
    }

    if (r < 32) {
        #pragma unroll
        for (int i = 0; i < 8; i++) {
            int n = m0 + ty*8 + i;
            if (n < NN && g_used[n*RR + r]) {
                float4 v = make_float4(acc[i][0], acc[i][1], acc[i][2], acc[i][3]);
                *(float4*)&g_xr2[(n*RR + r)*HID + tx*4] = v;
            }
        }
    } else {
        float4 bb = *(const float4*)&b2[tx*4];
        #pragma unroll
        for (int i = 0; i < 8; i++) {
            int n = m0 + ty*8 + i;
            if (n < NN) {
                float4 v = make_float4(acc[i][0] + bb.x, acc[i][1] + bb.y,
                                       acc[i][2] + bb.z, acc[i][3] + bb.w);
                *(float4*)&out[n*HID + tx*4] = v;
            }
        }
    }
}

// ---------------------------------------------------------------- layer-2 edge gather (warp/edge)
__global__ void k_edge2(const int* __restrict__ ei, const int* __restrict__ et,
                        float* __restrict__ out) {
    int gid  = blockIdx.x * blockDim.x + threadIdx.x;
    int e    = gid >> 5;
    int lane = gid & 31;
    if (e >= NE) return;
    int src = ei[e];
    int dst = ei[NE + e];
    int r   = et[e];
    float s = g_inv[dst*RR + r];
    float4 v = *(const float4*)&g_xr2[(src*RR + r)*HID + lane*4];
    float* o = &out[dst*HID + lane*4];
    atomicAdd(o + 0, s * v.x);
    atomicAdd(o + 1, s * v.y);
    atomicAdd(o + 2, s * v.z);
    atomicAdd(o + 3, s * v.w);
}

// ---------------------------------------------------------------- launch
extern "C" void kernel_launch(void* const* d_in, const int* in_sizes, int n_in,
                              void* d_out, int out_size) {
    const int* ei    = (const int*)d_in[0];            // edge_index [2, E] int32
    const int* et    = (const int*)d_in[1];            // edge_type  [E]    int32
    const float* x   = (const float*)d_in[2];          // node_emb [N, 16]
    const float* W1  = (const float*)d_in[3];          // [32, 16, 128]
    const float* r1  = (const float*)d_in[4];          // [16, 128]
    const float* b1  = (const float*)d_in[5];          // [128]
    const float* W2  = (const float*)d_in[6];          // [32, 128, 128]
    const float* r2  = (const float*)d_in[7];          // [128, 128]
    const float* b2  = (const float*)d_in[8];          // [128]
    float* out = (float*)d_out;                        // [20000, 128]

    k_zero    <<<512, 256>>>();
    k_count   <<<(NE + 255)/256, 256>>>(ei, et);
    k_inv     <<<(NRB + 255)/256, 256>>>();
    k_scatter1<<<(NE*4 + 255)/256, 256>>>(ei, et, x);
    k_layer1  <<<(NN + 63)/64, 256>>>(x, W1, r1, b1);
    dim3 g2((NN + 63)/64, 33);
    k_layer2  <<<g2, 256>>>(W2, r2, b2, out);
    k_edge2   <<<(NE*32 + 255)/256, 256>>>(ei, et, out);
}

// round 8
// speedup vs baseline: 2.6124x; 2.6124x over previous
#include <cuda_runtime.h>
#include <cstdint>

#define NN   20000
#define RR   32
#define EMB  16
#define HID  128
#define NE   600000
#define NRB  (NN*RR)          // 640000 (dst,rel) buckets

// ---- scratch (device globals; no allocation in kernel_launch) ----
__device__ float g_inv[NRB];                    // 1/count per (node, rel)
__device__ float g_m1 [NN*RR*EMB];              // layer-1 pre-aggregation  (41 MB)
__device__ float g_h1 [NN*HID];                 // layer-1 output           (10 MB)
__device__ float g_xr2[NN*RR*HID];              // layer-2 transformed feats (327 MB)
__device__ unsigned char g_used[NRB];           // (src, rel) pair appears on some edge

// ---------------------------------------------------------------- helpers
__device__ __forceinline__ uint32_t f2tf32(float f) {
    uint32_t r;
    asm("cvt.rna.tf32.f32 %0, %1;" : "=r"(r) : "f"(f));
    return r;
}

__device__ __forceinline__ void mma_tf32(float* d, const uint32_t* a, const uint32_t* b) {
    asm volatile("mma.sync.aligned.m16n8k8.row.col.f32.tf32.tf32.f32 "
                 "{%0,%1,%2,%3}, {%4,%5,%6,%7}, {%8,%9}, {%0,%1,%2,%3};"
                 : "+f"(d[0]), "+f"(d[1]), "+f"(d[2]), "+f"(d[3])
                 : "r"(a[0]), "r"(a[1]), "r"(a[2]), "r"(a[3]),
                   "r"(b[0]), "r"(b[1]));
}

// ---------------------------------------------------------------- zero scratch
__global__ void k_zero() {
    int i  = blockIdx.x * blockDim.x + threadIdx.x;
    int st = gridDim.x * blockDim.x;
    float4 z4 = make_float4(0.f, 0.f, 0.f, 0.f);
    for (int j = i; j < (NN*RR*EMB)/4; j += st) ((float4*)g_m1)[j] = z4;
    for (int j = i; j < NRB; j += st) { g_inv[j] = 0.f; g_used[j] = 0; }
}

// ---------------------------------------------------------------- edge counts + used mask
__global__ void k_count(const int* __restrict__ ei, const int* __restrict__ et) {
    int e = blockIdx.x * blockDim.x + threadIdx.x;
    if (e >= NE) return;
    int src = ei[e];
    int dst = ei[NE + e];
    int r   = et[e];
    atomicAdd(&g_inv[dst*RR + r], 1.f);
    g_used[src*RR + r] = 1;
}

__global__ void k_inv() {
    int i = blockIdx.x * blockDim.x + threadIdx.x;
    if (i >= NRB) return;
    float c = g_inv[i];
    g_inv[i] = (c > 0.f) ? 1.f / c : 0.f;
}

// ---------------------------------------------------------------- layer-1 edge scatter (4 thr/edge)
__global__ void k_scatter1(const int* __restrict__ ei, const int* __restrict__ et,
                           const float* __restrict__ x) {
    int idx = blockIdx.x * blockDim.x + threadIdx.x;
    if (idx >= NE * 4) return;
    int e = idx >> 2, q = idx & 3;
    int src = ei[e];
    int dst = ei[NE + e];
    int r   = et[e];
    float4 v = *(const float4*)&x[src*EMB + q*4];
    float* m = &g_m1[(dst*RR + r)*EMB + q*4];
    atomicAdd(m + 0, v.x); atomicAdd(m + 1, v.y);
    atomicAdd(m + 2, v.z); atomicAdd(m + 3, v.w);
}

// ---------------------------------------------------------------- layer-1 GEMM (tf32 mma)
// h1 = relu( [inv-scaled m1 | x] @ [W1 ; root1] + b1 )
// M = 20000, K = 528 (33 steps of 16), N = 128.  Tile 128x128, 256 thr, 8 warps (4x2).
__global__ void k_layer1(const float* __restrict__ x,  const float* __restrict__ W1,
                         const float* __restrict__ r1, const float* __restrict__ b1) {
    __shared__ uint32_t As[128][20];    // pad 20: conflict-free A-frag reads
    __shared__ uint32_t Bs[16][136];    // pad 136: conflict-free B-frag reads
    int m0   = blockIdx.x * 128;
    int tid  = threadIdx.x;
    int wid  = tid >> 5, lane = tid & 31;
    int wm   = wid & 3,  wn   = wid >> 2;     // 4 warps in M, 2 in N
    int gr   = lane >> 2, tg = lane & 3;

    float c[2][8][4];
    #pragma unroll
    for (int i = 0; i < 2; i++)
        #pragma unroll
        for (int j = 0; j < 8; j++)
            #pragma unroll
            for (int q = 0; q < 4; q++) c[i][j][q] = 0.f;

    int arow = tid >> 1, akg = (tid & 1) << 3;
    int gm   = m0 + arow;
    int bk   = tid >> 4, bc = (tid & 15) << 3;

    for (int step = 0; step < 33; ++step) {
        float av[8];
        #pragma unroll
        for (int i = 0; i < 8; i++) av[i] = 0.f;
        if (gm < NN) {
            if (step < 32) {
                float s = g_inv[gm*RR + step];
                if (s != 0.f) {
                    float4 p = *(const float4*)&g_m1[gm*(RR*EMB) + step*EMB + akg];
                    float4 q = *(const float4*)&g_m1[gm*(RR*EMB) + step*EMB + akg + 4];
                    av[0]=p.x*s; av[1]=p.y*s; av[2]=p.z*s; av[3]=p.w*s;
                    av[4]=q.x*s; av[5]=q.y*s; av[6]=q.z*s; av[7]=q.w*s;
                }
            } else {
                float4 p = *(const float4*)&x[gm*EMB + akg];
                float4 q = *(const float4*)&x[gm*EMB + akg + 4];
                av[0]=p.x; av[1]=p.y; av[2]=p.z; av[3]=p.w;
                av[4]=q.x; av[5]=q.y; av[6]=q.z; av[7]=q.w;
            }
        }
        const float* Bsrc = (step < 32) ? (W1 + step*(EMB*HID)) : r1;
        float4 u = *(const float4*)&Bsrc[bk*HID + bc];
        float4 v = *(const float4*)&Bsrc[bk*HID + bc + 4];

        __syncthreads();
        #pragma unroll
        for (int i = 0; i < 8; i++) As[arow][akg + i] = f2tf32(av[i]);
        Bs[bk][bc+0]=f2tf32(u.x); Bs[bk][bc+1]=f2tf32(u.y);
        Bs[bk][bc+2]=f2tf32(u.z); Bs[bk][bc+3]=f2tf32(u.w);
        Bs[bk][bc+4]=f2tf32(v.x); Bs[bk][bc+5]=f2tf32(v.y);
        Bs[bk][bc+6]=f2tf32(v.z); Bs[bk][bc+7]=f2tf32(v.w);
        __syncthreads();

        #pragma unroll
        for (int kc = 0; kc < 2; ++kc) {
            int k0 = kc << 3;
            uint32_t a[2][4], b[8][2];
            #pragma unroll
            for (int mt = 0; mt < 2; ++mt) {
                int mr = wm*32 + mt*16;
                a[mt][0] = As[mr+gr  ][k0+tg  ];
                a[mt][1] = As[mr+gr+8][k0+tg  ];
                a[mt][2] = As[mr+gr  ][k0+tg+4];
                a[mt][3] = As[mr+gr+8][k0+tg+4];
            }
            #pragma unroll
            for (int nt = 0; nt < 8; ++nt) {
                int nc = wn*64 + nt*8 + gr;
                b[nt][0] = Bs[k0+tg  ][nc];
                b[nt][1] = Bs[k0+tg+4][nc];
            }
            #pragma unroll
            for (int mt = 0; mt < 2; ++mt)
                #pragma unroll
                for (int nt = 0; nt < 8; ++nt)
                    mma_tf32(c[mt][nt], a[mt], b[nt]);
        }
    }

    #pragma unroll
    for (int mt = 0; mt < 2; ++mt) {
        #pragma unroll
        for (int half = 0; half < 2; ++half) {
            int rr = m0 + wm*32 + mt*16 + gr + half*8;
            if (rr < NN) {
                #pragma unroll
                for (int nt = 0; nt < 8; ++nt) {
                    int col = wn*64 + nt*8 + tg*2;
                    float v0 = c[mt][nt][half*2+0] + b1[col];
                    float v1 = c[mt][nt][half*2+1] + b1[col+1];
                    float2 o = make_float2(fmaxf(v0, 0.f), fmaxf(v1, 0.f));
                    *(float2*)&g_h1[rr*HID + col] = o;
                }
            }
        }
    }
}

// ---------------------------------------------------------------- layer-2 GEMM (tf32 mma)
// blockIdx.y = r (< 32): xr2[:,r,:] = h1 @ W2[r]  (store only used (n,r) rows)
// blockIdx.y = 32      : out        = h1 @ root2 + b2
__global__ void k_layer2(const float* __restrict__ W2, const float* __restrict__ r2,
                         const float* __restrict__ b2, float* __restrict__ out) {
    __shared__ uint32_t As[128][20];
    __shared__ uint32_t Bs[16][136];
    int m0   = blockIdx.x * 128;
    int rel  = blockIdx.y;
    int tid  = threadIdx.x;
    int wid  = tid >> 5, lane = tid & 31;
    int wm   = wid & 3,  wn   = wid >> 2;
    int gr   = lane >> 2, tg = lane & 3;
    const float* Bbase = (rel < 32) ? (W2 + rel*(HID*HID)) : r2;

    float c[2][8][4];
    #pragma unroll
    for (int i = 0; i < 2; i++)
        #pragma unroll
        for (int j = 0; j < 8; j++)
            #pragma unroll
            for (int q = 0; q < 4; q++) c[i][j][q] = 0.f;

    int arow = tid >> 1, akg = (tid & 1) << 3;
    int gm   = m0 + arow;
    int bk   = tid >> 4, bc = (tid & 15) << 3;

    for (int step = 0; step < 8; ++step) {
        float av[8];
        #pragma unroll
        for (int i = 0; i < 8; i++) av[i] = 0.f;
        if (gm < NN) {
            float4 p = *(const float4*)&g_h1[gm*HID + step*16 + akg];
            float4 q = *(const float4*)&g_h1[gm*HID + step*16 + akg + 4];
            av[0]=p.x; av[1]=p.y; av[2]=p.z; av[3]=p.w;
            av[4]=q.x; av[5]=q.y; av[6]=q.z; av[7]=q.w;
        }
        const float* Bsrc = Bbase + step*16*HID;
        float4 u = *(const float4*)&Bsrc[bk*HID + bc];
        float4 v = *(const float4*)&Bsrc[bk*HID + bc + 4];

        __syncthreads();
        #pragma unroll
        for (int i = 0; i < 8; i++) As[arow][akg + i] = f2tf32(av[i]);
        Bs[bk][bc+0]=f2tf32(u.x); Bs[bk][bc+1]=f2tf32(u.y);
        Bs[bk][bc+2]=f2tf32(u.z); Bs[bk][bc+3]=f2tf32(u.w);
        Bs[bk][bc+4]=f2tf32(v.x); Bs[bk][bc+5]=f2tf32(v.y);
        Bs[bk][bc+6]=f2tf32(v.z); Bs[bk][bc+7]=f2tf32(v.w);
        __syncthreads();

        #pragma unroll
        for (int kc = 0; kc < 2; ++kc) {
            int k0 = kc << 3;
            uint32_t a[2][4], b[8][2];
            #pragma unroll
            for (int mt = 0; mt < 2; ++mt) {
                int mr = wm*32 + mt*16;
                a[mt][0] = As[mr+gr  ][k0+tg  ];
                a[mt][1] = As[mr+gr+8][k0+tg  ];
                a[mt][2] = As[mr+gr  ][k0+tg+4];
                a[mt][3] = As[mr+gr+8][k0+tg+4];
            }
            #pragma unroll
            for (int nt = 0; nt < 8; ++nt) {
                int nc = wn*64 + nt*8 + gr;
                b[nt][0] = Bs[k0+tg  ][nc];
                b[nt][1] = Bs[k0+tg+4][nc];
            }
            #pragma unroll
            for (int mt = 0; mt < 2; ++mt)
                #pragma unroll
                for (int nt = 0; nt < 8; ++nt)
                    mma_tf32(c[mt][nt], a[mt], b[nt]);
        }
    }

    if (rel < 32) {
        #pragma unroll
        for (int mt = 0; mt < 2; ++mt) {
            #pragma unroll
            for (int half = 0; half < 2; ++half) {
                int rr = m0 + wm*32 + mt*16 + gr + half*8;
                if (rr < NN && g_used[rr*RR + rel]) {
                    float* base = &g_xr2[(rr*RR + rel)*HID];
                    #pragma unroll
                    for (int nt = 0; nt < 8; ++nt) {
                        int col = wn*64 + nt*8 + tg*2;
                        float2 o = make_float2(c[mt][nt][half*2+0], c[mt][nt][half*2+1]);
                        *(float2*)&base[col] = o;
                    }
                }
            }
        }
    } else {
        #pragma unroll
        for (int mt = 0; mt < 2; ++mt) {
            #pragma unroll
            for (int half = 0; half < 2; ++half) {
                int rr = m0 + wm*32 + mt*16 + gr + half*8;
                if (rr < NN) {
                    #pragma unroll
                    for (int nt = 0; nt < 8; ++nt) {
                        int col = wn*64 + nt*8 + tg*2;
                        float2 o = make_float2(c[mt][nt][half*2+0] + b2[col],
                                               c[mt][nt][half*2+1] + b2[col+1]);
                        *(float2*)&out[rr*HID + col] = o;
                    }
                }
            }
        }
    }
}

// ---------------------------------------------------------------- layer-2 edge gather (warp/edge)
__global__ void k_edge2(const int* __restrict__ ei, const int* __restrict__ et,
                        float* __restrict__ out) {
    int gid  = blockIdx.x * blockDim.x + threadIdx.x;
    int e    = gid >> 5;
    int lane = gid & 31;
    if (e >= NE) return;
    int src = ei[e];
    int dst = ei[NE + e];
    int r   = et[e];
    float s = g_inv[dst*RR + r];
    float4 v = *(const float4*)&g_xr2[(src*RR + r)*HID + lane*4];
    float* o = &out[dst*HID + lane*4];
    atomicAdd(o + 0, s * v.x);
    atomicAdd(o + 1, s * v.y);
    atomicAdd(o + 2, s * v.z);
    atomicAdd(o + 3, s * v.w);
}

// ---------------------------------------------------------------- launch
extern "C" void kernel_launch(void* const* d_in, const int* in_sizes, int n_in,
                              void* d_out, int out_size) {
    const int* ei    = (const int*)d_in[0];            // edge_index [2, E] int32
    const int* et    = (const int*)d_in[1];            // edge_type  [E]    int32
    const float* x   = (const float*)d_in[2];          // node_emb [N, 16]
    const float* W1  = (const float*)d_in[3];          // [32, 16, 128]
    const float* r1  = (const float*)d_in[4];          // [16, 128]
    const float* b1  = (const float*)d_in[5];          // [128]
    const float* W2  = (const float*)d_in[6];          // [32, 128, 128]
    const float* r2  = (const float*)d_in[7];          // [128, 128]
    const float* b2  = (const float*)d_in[8];          // [128]
    float* out = (float*)d_out;                        // [20000, 128]

    k_zero    <<<512, 256>>>();
    k_count   <<<(NE + 255)/256, 256>>>(ei, et);
    k_inv     <<<(NRB + 255)/256, 256>>>();
    k_scatter1<<<(NE*4 + 255)/256, 256>>>(ei, et, x);
    k_layer1  <<<(NN + 127)/128, 256>>>(x, W1, r1, b1);
    dim3 g2((NN + 127)/128, 33);
    k_layer2  <<<g2, 256>>>(W2, r2, b2, out);
    k_edge2   <<<(NE*32 + 255)/256, 256>>>(ei, et, out);
}